// round 1
// baseline (speedup 1.0000x reference)
#include <cuda_runtime.h>

// DiffAugment: brightness -> saturation -> contrast -> translate (zero pad) -> cutout
// B=128, C=3, H=W=256, fp32. shift=32, cut=51 (half=25).
//
// Math identity used: global mean after brightness+saturation
//   == mean(x_raw, per batch) + (r_bright - 0.5)
// because saturation preserves the per-pixel channel mean and brightness is a
// constant offset. So pass 1 reduces RAW x (no dependency), pass 2 fuses all ops.

#define EPB 196608   // elements per batch = 3*256*256

__device__ float g_part[512];   // 4 partial sums per batch

__global__ void __launch_bounds__(256) sum_kernel(const float* __restrict__ x) {
    int blk = blockIdx.x;           // 0..511 : batch = blk>>2, quarter = blk&3
    int t = threadIdx.x;            // 0..255
    const float4* p = reinterpret_cast<const float4*>(x) + (size_t)blk * 12288 + t;
    float s = 0.f;
#pragma unroll
    for (int k = 0; k < 48; ++k) {
        float4 v = p[k * 256];
        s += (v.x + v.y) + (v.z + v.w);
    }
#pragma unroll
    for (int o = 16; o; o >>= 1) s += __shfl_down_sync(0xffffffffu, s, o);
    __shared__ float sh[8];
    if ((t & 31) == 0) sh[t >> 5] = s;
    __syncthreads();
    if (t < 8) {
        s = sh[t];
        s += __shfl_down_sync(0xffu, s, 4);
        s += __shfl_down_sync(0xffu, s, 2);
        s += __shfl_down_sync(0xffu, s, 1);
        if (t == 0) g_part[blk] = s;
    }
}

__global__ void __launch_bounds__(256) aug_kernel(
    const float* __restrict__ x,
    const float* __restrict__ rb, const float* __restrict__ rs, const float* __restrict__ rc,
    const int* __restrict__ txv, const int* __restrict__ tyv,
    const int* __restrict__ oxv, const int* __restrict__ oyv,
    float* __restrict__ out)
{
    int idx = blockIdx.x * 256 + threadIdx.x;   // 0 .. 2097151
    int w4 = idx & 63;          // which group of 4 columns
    int h  = (idx >> 6) & 255;
    int b  = idx >> 14;

    float rbm = __ldg(rb + b) - 0.5f;
    float s2  = __ldg(rs + b) * 2.0f;
    float cc  = __ldg(rc + b) + 0.5f;
    float g   = (g_part[4*b] + g_part[4*b+1] + g_part[4*b+2] + g_part[4*b+3])
                * (1.0f / 196608.0f) + rbm;

    int tx = __ldg(txv + b) - 32;
    int ty = __ldg(tyv + b) - 32;
    int ox = __ldg(oxv + b);
    int oy = __ldg(oyv + b);

    int src_h = h + tx;
    bool row_ok  = ((unsigned)src_h) < 256u;
    bool cut_row = (h >= ox - 25) && (h <= ox + 25);

    float r0[4], r1[4], r2[4];
    int w0 = w4 << 2;
    const float* xb = x + (size_t)b * EPB + src_h * 256;

#pragma unroll
    for (int j = 0; j < 4; ++j) {
        int w  = w0 + j;
        int sw = w + ty;
        bool ok = row_ok && ((unsigned)sw < 256u) &&
                  !(cut_row && (w >= oy - 25) && (w <= oy + 25));
        float a0 = 0.f, a1 = 0.f, a2 = 0.f;
        if (ok) {
            float v0 = xb[sw];
            float v1 = xb[sw + 65536];
            float v2 = xb[sw + 131072];
            float m  = (v0 + v1 + v2) * (1.0f / 3.0f);
            float mb = m + rbm;                          // mean after brightness
            // x2 = (v - m)*2rs + m + rbm ; x3 = (x2 - g)*(rc+0.5) + g
            a0 = fmaf(fmaf(v0 - m, s2, mb) - g, cc, g);
            a1 = fmaf(fmaf(v1 - m, s2, mb) - g, cc, g);
            a2 = fmaf(fmaf(v2 - m, s2, mb) - g, cc, g);
        }
        r0[j] = a0; r1[j] = a1; r2[j] = a2;
    }

    size_t ob = (size_t)b * EPB + h * 256 + w0;
    *reinterpret_cast<float4*>(out + ob)          = make_float4(r0[0], r0[1], r0[2], r0[3]);
    *reinterpret_cast<float4*>(out + ob + 65536)  = make_float4(r1[0], r1[1], r1[2], r1[3]);
    *reinterpret_cast<float4*>(out + ob + 131072) = make_float4(r2[0], r2[1], r2[2], r2[3]);
}

extern "C" void kernel_launch(void* const* d_in, const int* in_sizes, int n_in,
                              void* d_out, int out_size) {
    const float* x  = (const float*)d_in[0];
    const float* rb = (const float*)d_in[1];
    const float* rs = (const float*)d_in[2];
    const float* rc = (const float*)d_in[3];
    const int*   tx = (const int*)d_in[4];
    const int*   ty = (const int*)d_in[5];
    const int*   ox = (const int*)d_in[6];
    const int*   oy = (const int*)d_in[7];
    float* out = (float*)d_out;

    sum_kernel<<<512, 256>>>(x);
    aug_kernel<<<8192, 256>>>(x, rb, rs, rc, tx, ty, ox, oy, out);
}